// round 2
// baseline (speedup 1.0000x reference)
#include <cuda_runtime.h>
#include <cstdint>

#define NMAX 100000
#define HID 64

// Scratch: per-node precomputed affine terms.
// A[n] = x[n] @ W1[0:13] + pos[n] @ W1[13:16] + b1   (64 floats)
// B[n] = pos[n] @ W1[13:16]                          (64 floats)
// Edge message hidden: h = relu(A[src] - B[dst]); out = h @ W2 + b2; max over dst.
__device__ float g_A[NMAX * HID];
__device__ float g_B[NMAX * HID];
__device__ int g_is32;   // 1 if edge_index is int32, 0 if int64

__global__ void zero_kernel(float* __restrict__ out, int n) {
    int i = blockIdx.x * blockDim.x + threadIdx.x;
    if (i < n) out[i] = 0.0f;
}

// Detect edge_index element width. For int64 little-endian values < 2^31,
// every odd int32 word is 0. For int32 random indices, odd words are random
// (P[all 2048 odd words == 0] ~ (1e-5)^2048 ~ 0).
__global__ void detect_kernel(const int* __restrict__ e, long long n_words) {
    __shared__ int any;
    if (threadIdx.x == 0) any = 0;
    __syncthreads();
    long long lim = n_words < 4096 ? n_words : 4096;
    for (long long i = 1 + 2 * (long long)threadIdx.x; i < lim; i += 2 * blockDim.x)
        if (e[i] != 0) any = 1;
    __syncthreads();
    if (threadIdx.x == 0) g_is32 = any;
}

__global__ __launch_bounds__(256) void precompute_kernel(
    const float* __restrict__ x, const float* __restrict__ pos,
    const float* __restrict__ W1, const float* __restrict__ b1,
    int n_nodes)
{
    __shared__ float m[16][16];       // 16 nodes x 16 features
    __shared__ float W1s[16 * 64];
    __shared__ float b1s[64];
    int tid = threadIdx.x;
    int node0 = blockIdx.x * 16;

    {   // stage features: nl = tid/16 node, f = tid%16 feature
        int nl = tid >> 4, f = tid & 15;
        int node = node0 + nl;
        float v = 0.0f;
        if (node < n_nodes) {
            v = (f < 13) ? x[node * 13 + f] : pos[node * 3 + (f - 13)];
        }
        m[nl][f] = v;
    }
    #pragma unroll
    for (int j = 0; j < 4; j++) W1s[tid + j * 256] = W1[tid + j * 256];
    if (tid < 64) b1s[tid] = b1[tid];
    __syncthreads();

    int col = tid & 63;
    #pragma unroll
    for (int r = 0; r < 4; r++) {
        int nloc = r * 4 + (tid >> 6);
        int node = node0 + nloc;
        if (node >= n_nodes) continue;
        float accA = b1s[col];
        float accB = 0.0f;
        #pragma unroll
        for (int i = 0; i < 13; i++)
            accA = fmaf(m[nloc][i], W1s[i * 64 + col], accA);
        #pragma unroll
        for (int p = 0; p < 3; p++) {
            float wv = W1s[(13 + p) * 64 + col];
            float pv = m[nloc][13 + p];
            accA = fmaf(pv, wv, accA);
            accB = fmaf(pv, wv, accB);
        }
        g_A[node * 64 + col] = accA;
        g_B[node * 64 + col] = accB;
    }
}

// Packed dual-fp32 FMA (sm_100+): d.lo += a.lo*b.lo ; d.hi += a.hi*b.hi
__device__ __forceinline__ void fma2(unsigned long long& d,
                                     unsigned long long a,
                                     unsigned long long b) {
    asm("fma.rn.f32x2 %0, %1, %2, %0;" : "+l"(d) : "l"(a), "l"(b));
}

// Each warp processes 8 edges per iteration.
//  - Stage t[e][k] = relu(A[src_e][k] - B[dst_e][k]) into smem (per-warp 8x64).
//  - Register-tiled GEMV vs W2 (smem, transposed, padded rows): lane owns cols
//    (lane, lane+32) for all 8 edges; k paired into f32x2 lanes, halves summed
//    at the end (order-free reduction).
//  - Predicated int-atomicMax into out (valid: out>=0, only positive v written).
__global__ __launch_bounds__(256) void edge_kernel(
    const void* __restrict__ eidx_raw, long long E,
    const float* __restrict__ W2, const float* __restrict__ b2,
    float* __restrict__ out)
{
    __shared__ __align__(16) float W2t[64 * 66];   // [col][k], pad 66 to dodge conflicts
    __shared__ __align__(16) float tbuf[8][8 * 64]; // [warp][edge][k]
    int tid = threadIdx.x;

    for (int idx = tid; idx < 4096; idx += 256) {
        int k = idx >> 6, n = idx & 63;
        W2t[n * 66 + k] = W2[idx];
    }
    __syncthreads();

    int is32 = g_is32;
    const int*       e32 = (const int*)eidx_raw;
    const long long* e64 = (const long long*)eidx_raw;

    int lane = tid & 31;
    int w = tid >> 5;
    float* tb = tbuf[w];
    float bc0 = b2[lane];
    float bc1 = b2[lane + 32];

    long long n_iters = (E + 7) >> 3;
    long long wg = (long long)blockIdx.x * 8 + w;
    long long stride = (long long)gridDim.x * 8;

    const unsigned long long* w0p = (const unsigned long long*)&W2t[lane * 66];
    const unsigned long long* w1p = (const unsigned long long*)&W2t[(lane + 32) * 66];

    for (long long it = wg; it < n_iters; it += stride) {
        long long base = it << 3;
        long long rem = E - base;
        int cnt = (rem >= 8) ? 8 : (int)rem;

        // lanes 0-7 carry src ids, 8-15 carry dst ids (as int32)
        int i8 = lane & 7;
        int sd = 0;
        if (i8 < cnt) {
            long long pos_ = base + i8;
            if (lane < 8)
                sd = is32 ? e32[pos_] : (int)e64[pos_];
            else if (lane < 16)
                sd = is32 ? e32[E + pos_] : (int)e64[E + pos_];
        }

        int dsts[8];
        #pragma unroll
        for (int e = 0; e < 8; e++) {
            int se = __shfl_sync(0xffffffffu, sd, e);
            int de = __shfl_sync(0xffffffffu, sd, 8 + e);
            if (e < cnt) {
                dsts[e] = de;
                float a0 = g_A[se * 64 + lane];
                float a1 = g_A[se * 64 + 32 + lane];
                float q0 = g_B[de * 64 + lane];
                float q1 = g_B[de * 64 + 32 + lane];
                tb[e * 64 + lane]      = fmaxf(a0 - q0, 0.0f);
                tb[e * 64 + 32 + lane] = fmaxf(a1 - q1, 0.0f);
            } else {
                dsts[e] = -1;
                tb[e * 64 + lane]      = 0.0f;
                tb[e * 64 + 32 + lane] = 0.0f;
            }
        }
        __syncwarp();

        unsigned long long acc[8][2];
        #pragma unroll
        for (int e = 0; e < 8; e++) { acc[e][0] = 0ull; acc[e][1] = 0ull; }

        #pragma unroll
        for (int k2 = 0; k2 < 32; k2++) {
            unsigned long long w0 = w0p[k2];
            unsigned long long w1 = w1p[k2];
            #pragma unroll
            for (int e = 0; e < 8; e++) {
                unsigned long long t2 =
                    *(const unsigned long long*)&tb[e * 64 + 2 * k2];
                fma2(acc[e][0], t2, w0);
                fma2(acc[e][1], t2, w1);
            }
        }

        #pragma unroll
        for (int e = 0; e < 8; e++) {
            int d = dsts[e];
            if (d >= 0) {
                float v0 = __uint_as_float((unsigned)acc[e][0]) +
                           __uint_as_float((unsigned)(acc[e][0] >> 32)) + bc0;
                float v1 = __uint_as_float((unsigned)acc[e][1]) +
                           __uint_as_float((unsigned)(acc[e][1] >> 32)) + bc1;
                // out holds only values >= 0; positive-float int compare == float compare
                if (v0 > 0.0f)
                    atomicMax((int*)(out + d * 64 + lane), __float_as_int(v0));
                if (v1 > 0.0f)
                    atomicMax((int*)(out + d * 64 + 32 + lane), __float_as_int(v1));
            }
        }
        __syncwarp();   // tbuf reused next iteration
    }
}

extern "C" void kernel_launch(void* const* d_in, const int* in_sizes, int n_in,
                              void* d_out, int out_size) {
    const float* x   = (const float*)d_in[0];
    const float* pos = (const float*)d_in[1];
    const float* W1  = (const float*)d_in[2];
    const float* b1  = (const float*)d_in[3];
    const float* W2  = (const float*)d_in[4];
    const float* b2  = (const float*)d_in[5];
    const void*  eidx = d_in[6];

    int n_nodes = in_sizes[0] / 13;
    long long E = (long long)in_sizes[6] / 2;
    float* out = (float*)d_out;

    int zb = (out_size + 255) / 256;
    zero_kernel<<<zb, 256>>>(out, out_size);
    detect_kernel<<<1, 256>>>((const int*)eidx, 2 * E);
    precompute_kernel<<<(n_nodes + 15) / 16, 256>>>(x, pos, W1, b1, n_nodes);
    edge_kernel<<<1184, 256>>>(eidx, E, W2, b2, out);
}